// round 8
// baseline (speedup 1.0000x reference)
#include <cuda_runtime.h>
#include <math.h>

#define BB 64
#define SS 512
#define FF 128
#define UU 512
#define SIGDIM (FF + FF*FF)   /* 16512 */
#define NBF 8
#define TT (SS-1)             /* 511 */
#define BU (BB*UU)            /* 32768 */
#define KSTEP 16

typedef unsigned long long ull;

/* ---------------- packed f32x2 helpers ---------------- */
__device__ __forceinline__ ull fma2(ull a, ull b, ull c)
{
    ull d;
    asm("fma.rn.f32x2 %0, %1, %2, %3;" : "=l"(d) : "l"(a), "l"(b), "l"(c));
    return d;
}
__device__ __forceinline__ float2 unpack2(ull v)
{
    float2 f;
    asm("mov.b64 {%0,%1}, %2;" : "=f"(f.x), "=f"(f.y) : "l"(v));
    return f;
}
__device__ __forceinline__ ull pack2(float x, float y)
{
    ull r;
    asm("mov.b64 %0, {%1,%2};" : "=l"(r) : "f"(x), "f"(y));
    return r;
}

/* ---------------- scratch (no allocations allowed) ---------------- */
__device__ float g_sig[BB*SIGDIM];
__device__ float g_z1[BU];
__device__ float g_zs[BU];
__device__ float g_h2[BU];
__device__ float g_g3[BU];
__device__ float g_g4[BU];
__device__ float g_Ab[BB*FF];
__device__ float g_As[BB*FF*NBF];
__device__ float g_cur[BU];
__device__ float g_gates[4*BU];

/* ---------------- zero all atomic accumulators (vectorized) ---------------- */
__global__ void k_zero()
{
    int i = blockIdx.x * blockDim.x + threadIdx.x;
    int n = blockDim.x * gridDim.x;
    float4 z = make_float4(0.f, 0.f, 0.f, 0.f);
    for (int j = i; j < BB*SIGDIM/4; j += n) reinterpret_cast<float4*>(g_sig)[j] = z;
    for (int j = i; j < BU/4; j += n) {
        reinterpret_cast<float4*>(g_z1)[j] = z;
        reinterpret_cast<float4*>(g_zs)[j] = z;
        reinterpret_cast<float4*>(g_h2)[j] = z;
        reinterpret_cast<float4*>(g_g3)[j] = z;
        reinterpret_cast<float4*>(g_g4)[j] = z;
        reinterpret_cast<float4*>(g_cur)[j] = z;
    }
    for (int j = i; j < 4*BU/4; j += n) reinterpret_cast<float4*>(g_gates)[j] = z;
    for (int j = i; j < BB*FF*NBF/4; j += n) reinterpret_cast<float4*>(g_As)[j] = z;
    for (int j = i; j < BB*FF/4; j += n) reinterpret_cast<float4*>(g_Ab)[j] = z;
}

/* =================================================================
   Warp-broadcast FFMA2 GEMM core with register prefetch pipeline.
   CTA: 256 threads = 8 warps.  Tile: M=64 x N=128.
   warp w owns n in [16w,16w+16); lane l owns m in {2l,2l+1}.
   AMODE: 0 plain, 1 elu(A+aux), 2 A+aux, 3 concat [A*(1/S) | aux]
   BTRANS: 0 B is [K,N] row-major; 1 B is [N,K] row-major (use B^T)
   ================================================================= */
template<int AMODE, int BTRANS>
__device__ __forceinline__ void gemmW(
    const float* __restrict__ A, int lda, const float* __restrict__ aux,
    const float* __restrict__ Bw, int ldb, float* __restrict__ out, int ldo,
    int n0, int k0, int Kchunk)
{
    __shared__ __align__(16) float Adup[KSTEP][132];
    __shared__ __align__(16) float Bsh[KSTEP][132];
    int tid = threadIdx.x;
    int l = tid & 31;
    int nw = (tid >> 5) * 16;
    int am = tid >> 2, ak = (tid & 3) * 4;      /* A staging coords */
    int bk = tid >> 4, bn8 = (tid & 15) * 8;    /* B staging, BTRANS=0 */
    int bn = tid >> 1, bkq = (tid & 1) * 8;     /* B staging, BTRANS=1 */

    ull acc[2][8] = {{0,0,0,0,0,0,0,0},{0,0,0,0,0,0,0,0}};
    float4 aPre, bPre0, bPre1;

    auto loadA = [&](int kg, float4& av) {
        if (AMODE == 3) {
            int k = kg + ak;
            if (k < UU) {
                av = *reinterpret_cast<const float4*>(&A[(size_t)am*UU + k]);
                av.x *= (1.f/SS); av.y *= (1.f/SS);
                av.z *= (1.f/SS); av.w *= (1.f/SS);
            } else {
                av = *reinterpret_cast<const float4*>(&aux[(size_t)am*UU + k - UU]);
            }
        } else {
            av = *reinterpret_cast<const float4*>(&A[(size_t)am*lda + kg + ak]);
            if (AMODE >= 1) {
                float4 bv = *reinterpret_cast<const float4*>(&aux[kg + ak]);
                av.x += bv.x; av.y += bv.y; av.z += bv.z; av.w += bv.w;
                if (AMODE == 1) {
                    av.x = av.x > 0.f ? av.x : expm1f(av.x);
                    av.y = av.y > 0.f ? av.y : expm1f(av.y);
                    av.z = av.z > 0.f ? av.z : expm1f(av.z);
                    av.w = av.w > 0.f ? av.w : expm1f(av.w);
                }
            }
        }
    };
    auto loadB = [&](int kg, float4& b0, float4& b1) {
        if (!BTRANS) {
            const float* bp = &Bw[(size_t)(kg + bk)*ldb + n0 + bn8];
            b0 = *reinterpret_cast<const float4*>(bp);
            b1 = *reinterpret_cast<const float4*>(bp + 4);
        } else {
            const float* bp = &Bw[(size_t)(n0 + bn)*ldb + kg + bkq];
            b0 = *reinterpret_cast<const float4*>(bp);
            b1 = *reinterpret_cast<const float4*>(bp + 4);
        }
    };

    loadA(k0, aPre);
    loadB(k0, bPre0, bPre1);

    for (int kk = 0; kk < Kchunk; kk += KSTEP) {
        __syncthreads();
        /* store prefetched chunk to smem */
        *reinterpret_cast<float2*>(&Adup[ak+0][2*am]) = make_float2(aPre.x, aPre.x);
        *reinterpret_cast<float2*>(&Adup[ak+1][2*am]) = make_float2(aPre.y, aPre.y);
        *reinterpret_cast<float2*>(&Adup[ak+2][2*am]) = make_float2(aPre.z, aPre.z);
        *reinterpret_cast<float2*>(&Adup[ak+3][2*am]) = make_float2(aPre.w, aPre.w);
        if (!BTRANS) {
            *reinterpret_cast<float4*>(&Bsh[bk][bn8])     = bPre0;
            *reinterpret_cast<float4*>(&Bsh[bk][bn8 + 4]) = bPre1;
        } else {
            Bsh[bkq+0][bn] = bPre0.x; Bsh[bkq+1][bn] = bPre0.y;
            Bsh[bkq+2][bn] = bPre0.z; Bsh[bkq+3][bn] = bPre0.w;
            Bsh[bkq+4][bn] = bPre1.x; Bsh[bkq+5][bn] = bPre1.y;
            Bsh[bkq+6][bn] = bPre1.z; Bsh[bkq+7][bn] = bPre1.w;
        }
        __syncthreads();
        /* issue next chunk's global loads (latency overlapped with compute) */
        if (kk + KSTEP < Kchunk) {
            loadA(k0 + kk + KSTEP, aPre);
            loadB(k0 + kk + KSTEP, bPre0, bPre1);
        }
        /* inner compute */
        #pragma unroll
        for (int c = 0; c < KSTEP; c++) {
            ulonglong2 av = *reinterpret_cast<const ulonglong2*>(&Adup[c][4*l]);
            float4 f0 = *reinterpret_cast<const float4*>(&Bsh[c][nw]);
            float4 f1 = *reinterpret_cast<const float4*>(&Bsh[c][nw + 4]);
            float4 f2 = *reinterpret_cast<const float4*>(&Bsh[c][nw + 8]);
            float4 f3 = *reinterpret_cast<const float4*>(&Bsh[c][nw + 12]);
            ull b[8];
            b[0] = pack2(f0.x, f0.y); b[1] = pack2(f0.z, f0.w);
            b[2] = pack2(f1.x, f1.y); b[3] = pack2(f1.z, f1.w);
            b[4] = pack2(f2.x, f2.y); b[5] = pack2(f2.z, f2.w);
            b[6] = pack2(f3.x, f3.y); b[7] = pack2(f3.z, f3.w);
            #pragma unroll
            for (int p = 0; p < 8; p++) {
                acc[0][p] = fma2(av.x, b[p], acc[0][p]);
                acc[1][p] = fma2(av.y, b[p], acc[1][p]);
            }
        }
    }
    /* epilogue: atomics (split-K) */
    #pragma unroll
    for (int p = 0; p < 8; p++) {
        float2 v0 = unpack2(acc[0][p]);
        float2 v1 = unpack2(acc[1][p]);
        int col = n0 + nw + 2*p;
        atomicAdd(&out[(size_t)(2*l)  *ldo + col],     v0.x);
        atomicAdd(&out[(size_t)(2*l)  *ldo + col + 1], v0.y);
        atomicAdd(&out[(size_t)(2*l+1)*ldo + col],     v1.x);
        atomicAdd(&out[(size_t)(2*l+1)*ldo + col + 1], v1.y);
    }
}

/* ---------------- signature: s1 + s2, 4-way t-split -----------------
   P[t,i] = 0.5*(w[t,i]+w[t+1,i]) - w[0,i]; D[t,j] = w[t+1,j]-w[t,j]
   s2[i,j] = sum_t P[t,i]*D[t,j].   grid (2 m-tiles, 4 t-splits, 64 b). */
__global__ void __launch_bounds__(256, 2)
k_sig(const float* __restrict__ X, const float* __restrict__ tk)
{
    int i0 = blockIdx.x * 64;
    int ts = blockIdx.y;
    int b  = blockIdx.z;
    int tid = threadIdx.x;
    int l = tid & 31;
    int nw = (tid >> 5) * 16;
    const float* Xb = X + (size_t)b * SS * FF;
    float tk0 = __ldg(&tk[0]);

    __shared__ __align__(16) float Pdup[KSTEP][132];
    __shared__ __align__(16) float Dsh[KSTEP][132];
    __shared__ float w0sh[64];

    if (tid < 64) w0sh[tid] = tk0 * __ldg(&Xb[i0 + tid]);

    ull acc[2][8] = {{0,0,0,0,0,0,0,0},{0,0,0,0,0,0,0,0}};

    int tbeg = ts * 128;
    int tend = tbeg + 128; if (tend > TT) tend = TT;

    for (int t0 = tbeg; t0 < tend; t0 += KSTEP) {
        __syncthreads();
        int tt = tid >> 4;
        int t  = t0 + tt;
        bool valid = t < tend;
        float tkt  = 0.f, tkt1 = 0.f;
        if (valid) { tkt = __ldg(&tk[t]); tkt1 = __ldg(&tk[t+1]); }
        {
            int i4 = (tid & 15) * 4;
            float4 pv = make_float4(0.f, 0.f, 0.f, 0.f);
            if (valid) {
                float4 xi  = *reinterpret_cast<const float4*>(&Xb[(size_t)t*FF + i0 + i4]);
                float4 xi1 = *reinterpret_cast<const float4*>(&Xb[(size_t)(t+1)*FF + i0 + i4]);
                pv.x = 0.5f*(tkt*xi.x + tkt1*xi1.x) - w0sh[i4+0];
                pv.y = 0.5f*(tkt*xi.y + tkt1*xi1.y) - w0sh[i4+1];
                pv.z = 0.5f*(tkt*xi.z + tkt1*xi1.z) - w0sh[i4+2];
                pv.w = 0.5f*(tkt*xi.w + tkt1*xi1.w) - w0sh[i4+3];
            }
            *reinterpret_cast<float2*>(&Pdup[tt][2*(i4+0)]) = make_float2(pv.x, pv.x);
            *reinterpret_cast<float2*>(&Pdup[tt][2*(i4+1)]) = make_float2(pv.y, pv.y);
            *reinterpret_cast<float2*>(&Pdup[tt][2*(i4+2)]) = make_float2(pv.z, pv.z);
            *reinterpret_cast<float2*>(&Pdup[tt][2*(i4+3)]) = make_float2(pv.w, pv.w);
        }
        {
            int j8 = (tid & 15) * 8;
            float4 d0 = make_float4(0.f,0.f,0.f,0.f);
            float4 d1 = make_float4(0.f,0.f,0.f,0.f);
            if (valid) {
                float4 x0 = *reinterpret_cast<const float4*>(&Xb[(size_t)t*FF + j8]);
                float4 x1 = *reinterpret_cast<const float4*>(&Xb[(size_t)t*FF + j8 + 4]);
                float4 y0 = *reinterpret_cast<const float4*>(&Xb[(size_t)(t+1)*FF + j8]);
                float4 y1 = *reinterpret_cast<const float4*>(&Xb[(size_t)(t+1)*FF + j8 + 4]);
                d0.x = tkt1*y0.x - tkt*x0.x; d0.y = tkt1*y0.y - tkt*x0.y;
                d0.z = tkt1*y0.z - tkt*x0.z; d0.w = tkt1*y0.w - tkt*x0.w;
                d1.x = tkt1*y1.x - tkt*x1.x; d1.y = tkt1*y1.y - tkt*x1.y;
                d1.z = tkt1*y1.z - tkt*x1.z; d1.w = tkt1*y1.w - tkt*x1.w;
            }
            *reinterpret_cast<float4*>(&Dsh[tt][j8])     = d0;
            *reinterpret_cast<float4*>(&Dsh[tt][j8 + 4]) = d1;
        }
        __syncthreads();
        #pragma unroll
        for (int c = 0; c < KSTEP; c++) {
            ulonglong2 av = *reinterpret_cast<const ulonglong2*>(&Pdup[c][4*l]);
            float4 f0 = *reinterpret_cast<const float4*>(&Dsh[c][nw]);
            float4 f1 = *reinterpret_cast<const float4*>(&Dsh[c][nw + 4]);
            float4 f2 = *reinterpret_cast<const float4*>(&Dsh[c][nw + 8]);
            float4 f3 = *reinterpret_cast<const float4*>(&Dsh[c][nw + 12]);
            ull bb[8];
            bb[0] = pack2(f0.x, f0.y); bb[1] = pack2(f0.z, f0.w);
            bb[2] = pack2(f1.x, f1.y); bb[3] = pack2(f1.z, f1.w);
            bb[4] = pack2(f2.x, f2.y); bb[5] = pack2(f2.z, f2.w);
            bb[6] = pack2(f3.x, f3.y); bb[7] = pack2(f3.z, f3.w);
            #pragma unroll
            for (int p = 0; p < 8; p++) {
                acc[0][p] = fma2(av.x, bb[p], acc[0][p]);
                acc[1][p] = fma2(av.y, bb[p], acc[1][p]);
            }
        }
    }

    float* dst = g_sig + (size_t)b*SIGDIM + FF;
    #pragma unroll
    for (int p = 0; p < 8; p++) {
        float2 v0 = unpack2(acc[0][p]);
        float2 v1 = unpack2(acc[1][p]);
        int col = nw + 2*p;
        atomicAdd(&dst[(size_t)(i0 + 2*l)    *FF + col],     v0.x);
        atomicAdd(&dst[(size_t)(i0 + 2*l)    *FF + col + 1], v0.y);
        atomicAdd(&dst[(size_t)(i0 + 2*l + 1)*FF + col],     v1.x);
        atomicAdd(&dst[(size_t)(i0 + 2*l + 1)*FF + col + 1], v1.y);
    }
    if (blockIdx.x == 0 && ts == 0 && tid < FF) {
        g_sig[(size_t)b*SIGDIM + tid] =
            __ldg(&tk[SS-1]) * Xb[(size_t)(SS-1)*FF + tid] - tk0 * Xb[tid];
    }
}

/* z1 = sig@w1, zs = sig@ws   grid (4 ntiles, 43 ksplit, 2) Kchunk 384 */
__global__ void __launch_bounds__(256, 2)
k_siggemm(const float* __restrict__ w1, const float* __restrict__ ws)
{
    const float* w = blockIdx.z ? ws : w1;
    float* o       = blockIdx.z ? g_zs : g_z1;
    gemmW<0,0>(g_sig, SIGDIM, nullptr, w, UU, o, UU,
               blockIdx.x * 128, blockIdx.y * 384, 384);
}

/* h2 = elu(z1+b1)@w2   grid (4, 32) Kchunk 16 */
__global__ void __launch_bounds__(256, 2)
k_h2(const float* __restrict__ b1, const float* __restrict__ w2)
{
    gemmW<1,0>(g_z1, UU, b1, w2, UU, g_h2, UU,
               blockIdx.x * 128, blockIdx.y * 16, 16);
}

/* g3 = (h2+b2)@w3, g4 = (h2+b2)@w4   grid (4, 16, 2) Kchunk 32 */
__global__ void __launch_bounds__(256, 2)
k_g34(const float* __restrict__ b2,
      const float* __restrict__ w3, const float* __restrict__ w4)
{
    const float* w = blockIdx.z ? w4 : w3;
    float* o       = blockIdx.z ? g_g4 : g_g3;
    gemmW<2,0>(g_h2, UU, b2, w, UU, o, UU,
               blockIdx.x * 128, blockIdx.y * 32, 32);
}

/* fused: glu+skip+LN+softmax -> attn (smem) -> attn-weighted silu/spline
   reductions.  grid 64 (one block per batch), 512 threads. */
__global__ void __launch_bounds__(512, 2)
k_lnsm_reduce(const float* __restrict__ b3, const float* __restrict__ b4,
              const float* __restrict__ bs, const float* __restrict__ gamma,
              const float* __restrict__ beta,
              const float* __restrict__ X, const float* __restrict__ tk)
{
    __shared__ float sm[32];
    __shared__ float bc0, bc1;
    __shared__ float attn_sh[UU];
    __shared__ float tk_sh[SS];
    int b = blockIdx.x, u = threadIdx.x;
    int w = u >> 5, l = u & 31;
    int idx = b * UU + u;

    tk_sh[u] = __ldg(&tk[u]);

    float g3v = g_g3[idx] + b3[u];
    float g4v = g_g4[idx] + b4[u];
    float y = g_zs[idx] + bs[u] + g4v / (1.f + __expf(-g3v));

    float s = y, q = y * y;
    #pragma unroll
    for (int o = 16; o; o >>= 1) {
        s += __shfl_xor_sync(0xffffffffu, s, o);
        q += __shfl_xor_sync(0xffffffffu, q, o);
    }
    if (l == 0) { sm[w] = s; sm[16 + w] = q; }
    __syncthreads();
    if (u < 32) {
        float v = sm[u];
        #pragma unroll
        for (int o = 8; o; o >>= 1) v += __shfl_xor_sync(0xffffffffu, v, o);
        if (u == 0)  bc0 = v;
        if (u == 16) bc1 = v;
    }
    __syncthreads();
    float mu  = bc0 * (1.f / UU);
    float var = bc1 * (1.f / UU) - mu * mu;
    float yn = (y - mu) * rsqrtf(var + 1e-3f) * gamma[u] + beta[u];

    float mx = yn;
    #pragma unroll
    for (int o = 16; o; o >>= 1) mx = fmaxf(mx, __shfl_xor_sync(0xffffffffu, mx, o));
    if (l == 0) sm[w] = mx;
    __syncthreads();
    if (w == 0) {
        float v = (l < 16) ? sm[l] : -3e38f;
        #pragma unroll
        for (int o = 8; o; o >>= 1) v = fmaxf(v, __shfl_xor_sync(0xffffffffu, v, o));
        if (l == 0) bc0 = v;
    }
    __syncthreads();
    float e = __expf(yn - bc0);
    float es = e;
    #pragma unroll
    for (int o = 16; o; o >>= 1) es += __shfl_xor_sync(0xffffffffu, es, o);
    if (l == 0) sm[w] = es;
    __syncthreads();
    if (w == 0) {
        float v = (l < 16) ? sm[l] : 0.f;
        #pragma unroll
        for (int o = 8; o; o >>= 1) v += __shfl_xor_sync(0xffffffffu, v, o);
        if (l == 0) bc1 = v;
    }
    __syncthreads();
    attn_sh[u] = e / bc1;
    __syncthreads();

    /* ---- attn-weighted reductions over s: thread = (s-chunk, f) ---- */
    int f  = u & 127;
    int sc = u >> 7;                 /* 0..3, each covers 128 s values */
    const float* Xb = X + (size_t)b * SS * FF;
    float accb = 0.f;
    float accs[NBF] = {};
    for (int ss = 0; ss < 128; ss++) {
        int sidx = sc * 128 + ss;
        float a  = attn_sh[sidx];
        float xv = tk_sh[sidx] * __ldg(&Xb[(size_t)sidx * FF + f]);
        float sg = 1.f / (1.f + __expf(-xv));
        accb += a * (xv * sg);
        float xs = (xv + 2.2f) * 2.5f;
        float mf = floorf(xs);
        int m = (int)mf;
        float uu = xs - mf;
        float um = 1.f - uu;
        float wd0 = uu*uu*uu * (1.f/6.f);
        float wd1 = 0.66666667f + um*um*(0.5f*um - 1.f);
        float wd2 = 0.66666667f + uu*uu*(0.5f*uu - 1.f);
        float wd3 = um*um*um * (1.f/6.f);
        #pragma unroll
        for (int k = 0; k < NBF; k++) {
            int d = m - k;
            float wv = (d == 0) ? wd0 : (d == 1) ? wd1 : (d == 2) ? wd2
                     : (d == 3) ? wd3 : 0.f;
            accs[k] += a * wv;
        }
    }
    atomicAdd(&g_Ab[b * FF + f], accb);
    #pragma unroll
    for (int k = 0; k < NBF; k++)
        atomicAdd(&g_As[(size_t)(b * FF + f) * NBF + k], accs[k]);
}

/* current*S = Ab@base_w + As . spline_w   grid (4 ntiles, 18 parts) */
__global__ void __launch_bounds__(256, 2)
k_cur(const float* __restrict__ base_w, const float* __restrict__ spline_w)
{
    int n0 = blockIdx.x * 128;
    int part = blockIdx.y;
    if (part < 2)
        gemmW<0,0>(g_Ab, FF, nullptr, base_w, UU, g_cur, UU,
                   n0, part * 64, 64);
    else
        gemmW<0,1>(g_As, FF * NBF, nullptr, spline_w, FF * NBF, g_cur, UU,
                   n0, (part - 2) * 64, 64);
}

/* 4 gate GEMMs, A = [cur/S | h_prev] built in A-load   grid (4, 4, 8) */
__global__ void __launch_bounds__(256, 2)
k_lstm(const float* __restrict__ h_prev,
       const float* __restrict__ wf, const float* __restrict__ wi,
       const float* __restrict__ wc, const float* __restrict__ wo)
{
    const float* w = (blockIdx.y == 0) ? wf : (blockIdx.y == 1) ? wi
                   : (blockIdx.y == 2) ? wc : wo;
    float* o = g_gates + (size_t)blockIdx.y * BU;
    gemmW<3,0>(g_cur, UU, h_prev, w, UU, o, UU,
               blockIdx.x * 128, blockIdx.z * 128, 128);
}

/* gate nonlinearities + state update */
__global__ void k_fin(const float* __restrict__ c_prev,
                      const float* __restrict__ bf, const float* __restrict__ bi,
                      const float* __restrict__ bc, const float* __restrict__ bo,
                      float* __restrict__ out, int out_size)
{
    int i = blockIdx.x * blockDim.x + threadIdx.x;
    int u = i & (UU - 1);
    float fg = 1.f / (1.f + __expf(-(g_gates[i]          + bf[u])));
    float ig = 1.f / (1.f + __expf(-(g_gates[BU + i]     + bi[u])));
    float cd = tanhf(              g_gates[2 * BU + i]   + bc[u]);
    float og = 1.f / (1.f + __expf(-(g_gates[3 * BU + i] + bo[u])));
    float c = fg * c_prev[i] + ig * cd;
    float h = og * tanhf(c);
    out[i] = h;
    if (out_size >= 2 * BU) out[BU + i] = c;
}

/* ------------------------------------------------------------------ */
extern "C" void kernel_launch(void* const* d_in, const int* in_sizes, int n_in,
                              void* d_out, int out_size)
{
    const float* X       = (const float*)d_in[0];
    const float* h_prev  = (const float*)d_in[1];
    const float* c_prev  = (const float*)d_in[2];
    const float* tk      = (const float*)d_in[3];
    const float* base_w  = (const float*)d_in[4];
    const float* spl_w   = (const float*)d_in[5];
    const float* w1      = (const float*)d_in[6];
    const float* b1      = (const float*)d_in[7];
    const float* w2      = (const float*)d_in[8];
    const float* b2      = (const float*)d_in[9];
    const float* w3      = (const float*)d_in[10];
    const float* b3      = (const float*)d_in[11];
    const float* w4      = (const float*)d_in[12];
    const float* b4      = (const float*)d_in[13];
    const float* ws      = (const float*)d_in[14];
    const float* bs      = (const float*)d_in[15];
    const float* gamma   = (const float*)d_in[16];
    const float* beta    = (const float*)d_in[17];
    const float* wf      = (const float*)d_in[18];
    const float* bf      = (const float*)d_in[19];
    const float* wi      = (const float*)d_in[20];
    const float* bi      = (const float*)d_in[21];
    const float* wc      = (const float*)d_in[22];
    const float* bc      = (const float*)d_in[23];
    const float* wo      = (const float*)d_in[24];
    const float* bo      = (const float*)d_in[25];
    float* out = (float*)d_out;

    k_zero       <<<512, 256>>>();
    k_sig        <<<dim3(2, 4, BB), 256>>>(X, tk);
    k_siggemm    <<<dim3(4, 43, 2), 256>>>(w1, ws);
    k_h2         <<<dim3(4, 32), 256>>>(b1, w2);
    k_g34        <<<dim3(4, 16, 2), 256>>>(b2, w3, w4);
    k_lnsm_reduce<<<BB, 512>>>(b3, b4, bs, gamma, beta, X, tk);
    k_cur        <<<dim3(4, 18), 256>>>(base_w, spl_w);
    k_lstm       <<<dim3(4, 4, 8), 256>>>(h_prev, wf, wi, wc, wo);
    k_fin        <<<BU / 256, 256>>>(c_prev, bf, bi, bc, bo, out, out_size);
}

// round 11
// speedup vs baseline: 1.3600x; 1.3600x over previous
#include <cuda_runtime.h>
#include <math.h>

#define BB 64
#define SS 512
#define FF 128
#define UU 512
#define SIGDIM (FF + FF*FF)   /* 16512 */
#define NBF 8
#define TT (SS-1)             /* 511 */
#define BU (BB*UU)            /* 32768 */
#define KSTEP 16

typedef unsigned long long ull;

/* ---------------- packed f32x2 helpers ---------------- */
__device__ __forceinline__ ull fma2(ull a, ull b, ull c)
{
    ull d;
    asm("fma.rn.f32x2 %0, %1, %2, %3;" : "=l"(d) : "l"(a), "l"(b), "l"(c));
    return d;
}
__device__ __forceinline__ float2 unpack2(ull v)
{
    float2 f;
    asm("mov.b64 {%0,%1}, %2;" : "=f"(f.x), "=f"(f.y) : "l"(v));
    return f;
}
__device__ __forceinline__ ull pack2(float x, float y)
{
    ull r;
    asm("mov.b64 %0, {%1,%2};" : "=l"(r) : "f"(x), "f"(y));
    return r;
}
__device__ __forceinline__ float tf32r(float x)
{
    unsigned r;
    asm("cvt.rna.tf32.f32 %0, %1;" : "=r"(r) : "f"(x));
    return __uint_as_float(r);
}
__device__ __forceinline__ unsigned tf32b(float x)
{
    unsigned r;
    asm("cvt.rna.tf32.f32 %0, %1;" : "=r"(r) : "f"(x));
    return r;
}

/* ---------------- scratch (no allocations allowed) ---------------- */
__device__ float g_sig[BB*SIGDIM];    /* stored pre-rounded to tf32 */
__device__ float g_z1[BU];
__device__ float g_zs[BU];
__device__ float g_h2[BU];
__device__ float g_g3[BU];
__device__ float g_g4[BU];
__device__ float g_attn[BU];
__device__ float g_Ab[BB*FF];
__device__ float g_As[BB*FF*NBF];
__device__ float g_cur[BU];
__device__ float g_gates[4*BU];

/* ---------------- zero the atomic accumulators ---------------- */
__global__ void k_zero()
{
    int i = blockIdx.x * blockDim.x + threadIdx.x;
    int n = blockDim.x * gridDim.x;
    for (int j = i; j < BU; j += n) {
        g_z1[j] = 0.f; g_zs[j] = 0.f; g_h2[j] = 0.f;
        g_g3[j] = 0.f; g_g4[j] = 0.f; g_cur[j] = 0.f;
        g_gates[j] = 0.f; g_gates[BU + j] = 0.f;
        g_gates[2*BU + j] = 0.f; g_gates[3*BU + j] = 0.f;
    }
    for (int j = i; j < BB*FF*NBF; j += n) {
        g_As[j] = 0.f;
        if (j < BB*FF) g_Ab[j] = 0.f;
    }
}

/* =================================================================
   Warp-broadcast FFMA2 GEMM core (R6 version, no prefetch).
   CTA: 256 threads = 8 warps.  Tile: M=64 x N=128.
   AMODE: 0 plain, 1 elu(A+aux), 2 A+aux, 3 concat [A*(1/S) | aux]
   BTRANS: 0 B is [K,N] row-major; 1 B is [N,K] row-major (use B^T)
   ================================================================= */
template<int AMODE, int BTRANS>
__device__ __forceinline__ void gemmW(
    const float* __restrict__ A, int lda, const float* __restrict__ aux,
    const float* __restrict__ Bw, int ldb, float* __restrict__ out, int ldo,
    int n0, int k0, int Kchunk)
{
    __shared__ __align__(16) float Adup[KSTEP][132];
    __shared__ __align__(16) float Bsh[KSTEP][132];
    int tid = threadIdx.x;
    int l = tid & 31;
    int nw = (tid >> 5) * 16;
    ull acc[2][8] = {{0,0,0,0,0,0,0,0},{0,0,0,0,0,0,0,0}};

    for (int kk = 0; kk < Kchunk; kk += KSTEP) {
        int kg = k0 + kk;
        __syncthreads();
        {
            int m = tid >> 2, k4 = (tid & 3) * 4;
            float4 av;
            if (AMODE == 3) {
                int k = kg + k4;
                if (k < UU) {
                    av = *reinterpret_cast<const float4*>(&A[(size_t)m*UU + k]);
                    av.x *= (1.f/SS); av.y *= (1.f/SS);
                    av.z *= (1.f/SS); av.w *= (1.f/SS);
                } else {
                    av = *reinterpret_cast<const float4*>(&aux[(size_t)m*UU + k - UU]);
                }
            } else {
                av = *reinterpret_cast<const float4*>(&A[(size_t)m*lda + kg + k4]);
                if (AMODE >= 1) {
                    float4 bv = *reinterpret_cast<const float4*>(&aux[kg + k4]);
                    av.x += bv.x; av.y += bv.y; av.z += bv.z; av.w += bv.w;
                    if (AMODE == 1) {
                        av.x = av.x > 0.f ? av.x : expm1f(av.x);
                        av.y = av.y > 0.f ? av.y : expm1f(av.y);
                        av.z = av.z > 0.f ? av.z : expm1f(av.z);
                        av.w = av.w > 0.f ? av.w : expm1f(av.w);
                    }
                }
            }
            *reinterpret_cast<float2*>(&Adup[k4+0][2*m]) = make_float2(av.x, av.x);
            *reinterpret_cast<float2*>(&Adup[k4+1][2*m]) = make_float2(av.y, av.y);
            *reinterpret_cast<float2*>(&Adup[k4+2][2*m]) = make_float2(av.z, av.z);
            *reinterpret_cast<float2*>(&Adup[k4+3][2*m]) = make_float2(av.w, av.w);
        }
        if (!BTRANS) {
            int k = tid >> 4, n8 = (tid & 15) * 8;
            const float* bp = &Bw[(size_t)(kg + k)*ldb + n0 + n8];
            float4 b0 = *reinterpret_cast<const float4*>(bp);
            float4 b1 = *reinterpret_cast<const float4*>(bp + 4);
            *reinterpret_cast<float4*>(&Bsh[k][n8])     = b0;
            *reinterpret_cast<float4*>(&Bsh[k][n8 + 4]) = b1;
        } else {
            int n = tid >> 1, kq = (tid & 1) * 8;
            const float* bp = &Bw[(size_t)(n0 + n)*ldb + kg + kq];
            float4 b0 = *reinterpret_cast<const float4*>(bp);
            float4 b1 = *reinterpret_cast<const float4*>(bp + 4);
            Bsh[kq+0][n] = b0.x; Bsh[kq+1][n] = b0.y;
            Bsh[kq+2][n] = b0.z; Bsh[kq+3][n] = b0.w;
            Bsh[kq+4][n] = b1.x; Bsh[kq+5][n] = b1.y;
            Bsh[kq+6][n] = b1.z; Bsh[kq+7][n] = b1.w;
        }
        __syncthreads();
        #pragma unroll
        for (int c = 0; c < KSTEP; c++) {
            ulonglong2 av = *reinterpret_cast<const ulonglong2*>(&Adup[c][4*l]);
            float4 f0 = *reinterpret_cast<const float4*>(&Bsh[c][nw]);
            float4 f1 = *reinterpret_cast<const float4*>(&Bsh[c][nw + 4]);
            float4 f2 = *reinterpret_cast<const float4*>(&Bsh[c][nw + 8]);
            float4 f3 = *reinterpret_cast<const float4*>(&Bsh[c][nw + 12]);
            ull b[8];
            b[0] = pack2(f0.x, f0.y); b[1] = pack2(f0.z, f0.w);
            b[2] = pack2(f1.x, f1.y); b[3] = pack2(f1.z, f1.w);
            b[4] = pack2(f2.x, f2.y); b[5] = pack2(f2.z, f2.w);
            b[6] = pack2(f3.x, f3.y); b[7] = pack2(f3.z, f3.w);
            #pragma unroll
            for (int p = 0; p < 8; p++) {
                acc[0][p] = fma2(av.x, b[p], acc[0][p]);
                acc[1][p] = fma2(av.y, b[p], acc[1][p]);
            }
        }
    }
    #pragma unroll
    for (int p = 0; p < 8; p++) {
        float2 v0 = unpack2(acc[0][p]);
        float2 v1 = unpack2(acc[1][p]);
        int col = n0 + nw + 2*p;
        atomicAdd(&out[(size_t)(2*l)  *ldo + col],     v0.x);
        atomicAdd(&out[(size_t)(2*l)  *ldo + col + 1], v0.y);
        atomicAdd(&out[(size_t)(2*l+1)*ldo + col],     v1.x);
        atomicAdd(&out[(size_t)(2*l+1)*ldo + col + 1], v1.y);
    }
}

/* ---------------- signature: s1 + s2 (R6 direct-store version) -----
   Output rounded to tf32 (only consumer is the tensor-core siggemm). */
__global__ void k_sig(const float* __restrict__ X, const float* __restrict__ tk)
{
    int i0 = blockIdx.x * 64;
    int b  = blockIdx.y;
    int tid = threadIdx.x;
    int l = tid & 31;
    int nw = (tid >> 5) * 16;
    const float* Xb = X + (size_t)b * SS * FF;
    float tk0 = __ldg(&tk[0]);

    __shared__ __align__(16) float Pdup[KSTEP][132];
    __shared__ __align__(16) float Dsh[KSTEP][132];
    __shared__ float w0sh[64];

    if (tid < 64) w0sh[tid] = tk0 * __ldg(&Xb[i0 + tid]);

    ull acc[2][8] = {{0,0,0,0,0,0,0,0},{0,0,0,0,0,0,0,0}};

    for (int t0 = 0; t0 < TT; t0 += KSTEP) {
        __syncthreads();
        int tt = tid >> 4;
        int t  = t0 + tt;
        bool valid = t < TT;
        float tkt  = 0.f, tkt1 = 0.f;
        if (valid) { tkt = __ldg(&tk[t]); tkt1 = __ldg(&tk[t+1]); }
        {
            int i4 = (tid & 15) * 4;
            float4 pv = make_float4(0.f, 0.f, 0.f, 0.f);
            if (valid) {
                float4 xi  = *reinterpret_cast<const float4*>(&Xb[(size_t)t*FF + i0 + i4]);
                float4 xi1 = *reinterpret_cast<const float4*>(&Xb[(size_t)(t+1)*FF + i0 + i4]);
                pv.x = 0.5f*(tkt*xi.x + tkt1*xi1.x) - w0sh[i4+0];
                pv.y = 0.5f*(tkt*xi.y + tkt1*xi1.y) - w0sh[i4+1];
                pv.z = 0.5f*(tkt*xi.z + tkt1*xi1.z) - w0sh[i4+2];
                pv.w = 0.5f*(tkt*xi.w + tkt1*xi1.w) - w0sh[i4+3];
            }
            *reinterpret_cast<float2*>(&Pdup[tt][2*(i4+0)]) = make_float2(pv.x, pv.x);
            *reinterpret_cast<float2*>(&Pdup[tt][2*(i4+1)]) = make_float2(pv.y, pv.y);
            *reinterpret_cast<float2*>(&Pdup[tt][2*(i4+2)]) = make_float2(pv.z, pv.z);
            *reinterpret_cast<float2*>(&Pdup[tt][2*(i4+3)]) = make_float2(pv.w, pv.w);
        }
        {
            int j8 = (tid & 15) * 8;
            float4 d0 = make_float4(0.f,0.f,0.f,0.f);
            float4 d1 = make_float4(0.f,0.f,0.f,0.f);
            if (valid) {
                float4 x0 = *reinterpret_cast<const float4*>(&Xb[(size_t)t*FF + j8]);
                float4 x1 = *reinterpret_cast<const float4*>(&Xb[(size_t)t*FF + j8 + 4]);
                float4 y0 = *reinterpret_cast<const float4*>(&Xb[(size_t)(t+1)*FF + j8]);
                float4 y1 = *reinterpret_cast<const float4*>(&Xb[(size_t)(t+1)*FF + j8 + 4]);
                d0.x = tkt1*y0.x - tkt*x0.x; d0.y = tkt1*y0.y - tkt*x0.y;
                d0.z = tkt1*y0.z - tkt*x0.z; d0.w = tkt1*y0.w - tkt*x0.w;
                d1.x = tkt1*y1.x - tkt*x1.x; d1.y = tkt1*y1.y - tkt*x1.y;
                d1.z = tkt1*y1.z - tkt*x1.z; d1.w = tkt1*y1.w - tkt*x1.w;
            }
            *reinterpret_cast<float4*>(&Dsh[tt][j8])     = d0;
            *reinterpret_cast<float4*>(&Dsh[tt][j8 + 4]) = d1;
        }
        __syncthreads();
        #pragma unroll
        for (int c = 0; c < KSTEP; c++) {
            ulonglong2 av = *reinterpret_cast<const ulonglong2*>(&Pdup[c][4*l]);
            float4 f0 = *reinterpret_cast<const float4*>(&Dsh[c][nw]);
            float4 f1 = *reinterpret_cast<const float4*>(&Dsh[c][nw + 4]);
            float4 f2 = *reinterpret_cast<const float4*>(&Dsh[c][nw + 8]);
            float4 f3 = *reinterpret_cast<const float4*>(&Dsh[c][nw + 12]);
            ull bb[8];
            bb[0] = pack2(f0.x, f0.y); bb[1] = pack2(f0.z, f0.w);
            bb[2] = pack2(f1.x, f1.y); bb[3] = pack2(f1.z, f1.w);
            bb[4] = pack2(f2.x, f2.y); bb[5] = pack2(f2.z, f2.w);
            bb[6] = pack2(f3.x, f3.y); bb[7] = pack2(f3.z, f3.w);
            #pragma unroll
            for (int p = 0; p < 8; p++) {
                acc[0][p] = fma2(av.x, bb[p], acc[0][p]);
                acc[1][p] = fma2(av.y, bb[p], acc[1][p]);
            }
        }
    }

    float* dst = g_sig + (size_t)b*SIGDIM + FF;
    #pragma unroll
    for (int p = 0; p < 8; p++) {
        float2 v0 = unpack2(acc[0][p]);
        float2 v1 = unpack2(acc[1][p]);
        int col = nw + 2*p;
        dst[(size_t)(i0 + 2*l)    *FF + col]     = tf32r(v0.x);
        dst[(size_t)(i0 + 2*l)    *FF + col + 1] = tf32r(v0.y);
        dst[(size_t)(i0 + 2*l + 1)*FF + col]     = tf32r(v1.x);
        dst[(size_t)(i0 + 2*l + 1)*FF + col + 1] = tf32r(v1.y);
    }
    if (blockIdx.x == 0 && tid < FF) {
        g_sig[(size_t)b*SIGDIM + tid] = tf32r(
            __ldg(&tk[SS-1]) * Xb[(size_t)(SS-1)*FF + tid] - tk0 * Xb[tid]);
    }
}

/* =================================================================
   z1 = sig@w1, zs = sig@ws via tf32 mma.sync.m16n8k8.
   grid (8 ntiles of 64, 12 ksplit of 1376, 2 which), 128 threads.
   Warp w computes rows [16w,16w+16) x all 64 n (8 n-frags).
   A (g_sig) is pre-rounded tf32 bits; B converted during staging.
   smem pad 72 words -> fragment LDS provably conflict-free.
   ================================================================= */
__global__ void __launch_bounds__(128)
k_siggemm(const float* __restrict__ w1, const float* __restrict__ ws)
{
    const float* Bw = blockIdx.z ? ws : w1;
    float* o        = blockIdx.z ? g_zs : g_z1;
    int n0 = blockIdx.x * 64;
    int k0 = blockIdx.y * 1376;

    __shared__ __align__(16) unsigned As[32*72];
    __shared__ __align__(16) unsigned Bs[32*72];

    int tid  = threadIdx.x;
    int lane = tid & 31;
    int warp = tid >> 5;              /* 0..3 */
    int g  = lane >> 2, t4 = lane & 3;
    int m0w = warp * 16;

    float c[8][4];
    #pragma unroll
    for (int j = 0; j < 8; j++)
        { c[j][0]=0.f; c[j][1]=0.f; c[j][2]=0.f; c[j][3]=0.f; }

    const unsigned* A = reinterpret_cast<const unsigned*>(g_sig);
    int am = tid >> 1, akh = (tid & 1) * 16;
    int bk = tid >> 2, bnq = (tid & 3) * 16;

    for (int kk = 0; kk < 1376; kk += 32) {
        int kg = k0 + kk;
        __syncthreads();
        /* A stage: As[k][m], raw tf32-bit copy, transposed */
        {
            const unsigned* ap = &A[(size_t)am*SIGDIM + kg + akh];
            uint4 u0 = *reinterpret_cast<const uint4*>(ap);
            uint4 u1 = *reinterpret_cast<const uint4*>(ap + 4);
            uint4 u2 = *reinterpret_cast<const uint4*>(ap + 8);
            uint4 u3 = *reinterpret_cast<const uint4*>(ap + 12);
            As[(akh+ 0)*72 + am] = u0.x; As[(akh+ 1)*72 + am] = u0.y;
            As[(akh+ 2)*72 + am] = u0.z; As[(akh+ 3)*72 + am] = u0.w;
            As[(akh+ 4)*72 + am] = u1.x; As[(akh+ 5)*72 + am] = u1.y;
            As[(akh+ 6)*72 + am] = u1.z; As[(akh+ 7)*72 + am] = u1.w;
            As[(akh+ 8)*72 + am] = u2.x; As[(akh+ 9)*72 + am] = u2.y;
            As[(akh+10)*72 + am] = u2.z; As[(akh+11)*72 + am] = u2.w;
            As[(akh+12)*72 + am] = u3.x; As[(akh+13)*72 + am] = u3.y;
            As[(akh+14)*72 + am] = u3.z; As[(akh+15)*72 + am] = u3.w;
        }
        /* B stage: Bs[k][n], cvt to tf32 */
        {
            const float* bp = &Bw[(size_t)(kg + bk)*UU + n0 + bnq];
            float4 f0 = *reinterpret_cast<const float4*>(bp);
            float4 f1 = *reinterpret_cast<const float4*>(bp + 4);
            float4 f2 = *reinterpret_cast<const float4*>(bp + 8);
            float4 f3 = *reinterpret_cast<const float4*>(bp + 12);
            uint4 v0 = make_uint4(tf32b(f0.x), tf32b(f0.y), tf32b(f0.z), tf32b(f0.w));
            uint4 v1 = make_uint4(tf32b(f1.x), tf32b(f1.y), tf32b(f1.z), tf32b(f1.w));
            uint4 v2 = make_uint4(tf32b(f2.x), tf32b(f2.y), tf32b(f2.z), tf32b(f2.w));
            uint4 v3 = make_uint4(tf32b(f3.x), tf32b(f3.y), tf32b(f3.z), tf32b(f3.w));
            *reinterpret_cast<uint4*>(&Bs[bk*72 + bnq])      = v0;
            *reinterpret_cast<uint4*>(&Bs[bk*72 + bnq + 4])  = v1;
            *reinterpret_cast<uint4*>(&Bs[bk*72 + bnq + 8])  = v2;
            *reinterpret_cast<uint4*>(&Bs[bk*72 + bnq + 12]) = v3;
        }
        __syncthreads();
        #pragma unroll
        for (int ks = 0; ks < 4; ks++) {
            int kb = ks * 8;
            unsigned a0 = As[(kb+t4  )*72 + m0w + g];
            unsigned a1 = As[(kb+t4  )*72 + m0w + g + 8];
            unsigned a2 = As[(kb+t4+4)*72 + m0w + g];
            unsigned a3 = As[(kb+t4+4)*72 + m0w + g + 8];
            #pragma unroll
            for (int j = 0; j < 8; j++) {
                unsigned b0 = Bs[(kb+t4  )*72 + 8*j + g];
                unsigned b1 = Bs[(kb+t4+4)*72 + 8*j + g];
                asm volatile(
                    "mma.sync.aligned.m16n8k8.row.col.f32.tf32.tf32.f32 "
                    "{%0,%1,%2,%3}, {%4,%5,%6,%7}, {%8,%9}, {%0,%1,%2,%3};"
                    : "+f"(c[j][0]), "+f"(c[j][1]), "+f"(c[j][2]), "+f"(c[j][3])
                    : "r"(a0), "r"(a1), "r"(a2), "r"(a3), "r"(b0), "r"(b1));
            }
        }
    }
    #pragma unroll
    for (int j = 0; j < 8; j++) {
        int row = m0w + g;
        int col = n0 + 8*j + 2*t4;
        atomicAdd(&o[(size_t)row    *UU + col],     c[j][0]);
        atomicAdd(&o[(size_t)row    *UU + col + 1], c[j][1]);
        atomicAdd(&o[(size_t)(row+8)*UU + col],     c[j][2]);
        atomicAdd(&o[(size_t)(row+8)*UU + col + 1], c[j][3]);
    }
}

/* h2 = elu(z1+b1)@w2   grid (4, 16) Kchunk 32 */
__global__ void k_h2(const float* __restrict__ b1, const float* __restrict__ w2)
{
    gemmW<1,0>(g_z1, UU, b1, w2, UU, g_h2, UU,
               blockIdx.x * 128, blockIdx.y * 32, 32);
}

/* g3 = (h2+b2)@w3, g4 = (h2+b2)@w4   grid (4, 8, 2) Kchunk 64 */
__global__ void k_g34(const float* __restrict__ b2,
                      const float* __restrict__ w3, const float* __restrict__ w4)
{
    const float* w = blockIdx.z ? w4 : w3;
    float* o       = blockIdx.z ? g_g4 : g_g3;
    gemmW<2,0>(g_h2, UU, b2, w, UU, o, UU,
               blockIdx.x * 128, blockIdx.y * 64, 64);
}

/* glu + skip + layernorm + softmax -> attn   grid 64, 512 threads */
__global__ void k_lnsm(const float* __restrict__ b3, const float* __restrict__ b4,
                       const float* __restrict__ bs, const float* __restrict__ gamma,
                       const float* __restrict__ beta)
{
    __shared__ float sm[32];
    __shared__ float bc0, bc1;
    int b = blockIdx.x, u = threadIdx.x;
    int w = u >> 5, l = u & 31;
    int idx = b * UU + u;
    float g3v = g_g3[idx] + b3[u];
    float g4v = g_g4[idx] + b4[u];
    float y = g_zs[idx] + bs[u] + g4v / (1.f + __expf(-g3v));

    float s = y, q = y * y;
    #pragma unroll
    for (int o = 16; o; o >>= 1) {
        s += __shfl_xor_sync(0xffffffffu, s, o);
        q += __shfl_xor_sync(0xffffffffu, q, o);
    }
    if (l == 0) { sm[w] = s; sm[16 + w] = q; }
    __syncthreads();
    if (u < 32) {
        float v = sm[u];
        #pragma unroll
        for (int o = 8; o; o >>= 1) v += __shfl_xor_sync(0xffffffffu, v, o);
        if (u == 0)  bc0 = v;
        if (u == 16) bc1 = v;
    }
    __syncthreads();
    float mu  = bc0 * (1.f / UU);
    float var = bc1 * (1.f / UU) - mu * mu;
    float yn = (y - mu) * rsqrtf(var + 1e-3f) * gamma[u] + beta[u];

    float mx = yn;
    #pragma unroll
    for (int o = 16; o; o >>= 1) mx = fmaxf(mx, __shfl_xor_sync(0xffffffffu, mx, o));
    if (l == 0) sm[w] = mx;
    __syncthreads();
    if (w == 0) {
        float v = (l < 16) ? sm[l] : -3e38f;
        #pragma unroll
        for (int o = 8; o; o >>= 1) v = fmaxf(v, __shfl_xor_sync(0xffffffffu, v, o));
        if (l == 0) bc0 = v;
    }
    __syncthreads();
    float e = __expf(yn - bc0);
    float es = e;
    #pragma unroll
    for (int o = 16; o; o >>= 1) es += __shfl_xor_sync(0xffffffffu, es, o);
    if (l == 0) sm[w] = es;
    __syncthreads();
    if (w == 0) {
        float v = (l < 16) ? sm[l] : 0.f;
        #pragma unroll
        for (int o = 8; o; o >>= 1) v += __shfl_xor_sync(0xffffffffu, v, o);
        if (l == 0) bc1 = v;
    }
    __syncthreads();
    g_attn[idx] = e / bc1;
}

/* attn-weighted reductions; closed-form uniform cubic B-spline */
__global__ void k_reduce(const float* __restrict__ X, const float* __restrict__ tk)
{
    int b  = blockIdx.x;
    int s0 = blockIdx.y * 64;
    int f  = threadIdx.x;
    const float* Xb = X + (size_t)b * SS * FF;
    float accb = 0.f;
    float accs[NBF] = {};
    for (int ss = 0; ss < 64; ss++) {
        int s = s0 + ss;
        float a  = __ldg(&g_attn[b * UU + s]);
        float xv = __ldg(&tk[s]) * __ldg(&Xb[(size_t)s * FF + f]);
        float sg = 1.f / (1.f + __expf(-xv));
        accb += a * (xv * sg);
        float xs = (xv + 2.2f) * 2.5f;
        float mf = floorf(xs);
        int m = (int)mf;
        float u  = xs - mf;
        float um = 1.f - u;
        float wd0 = u*u*u * (1.f/6.f);
        float wd1 = 0.66666667f + um*um*(0.5f*um - 1.f);
        float wd2 = 0.66666667f + u*u*(0.5f*u - 1.f);
        float wd3 = um*um*um * (1.f/6.f);
        #pragma unroll
        for (int k = 0; k < NBF; k++) {
            int d = m - k;
            float wv = (d == 0) ? wd0 : (d == 1) ? wd1 : (d == 2) ? wd2
                     : (d == 3) ? wd3 : 0.f;
            accs[k] += a * wv;
        }
    }
    atomicAdd(&g_Ab[b * FF + f], accb);
    #pragma unroll
    for (int k = 0; k < NBF; k++)
        atomicAdd(&g_As[(size_t)(b * FF + f) * NBF + k], accs[k]);
}

/* current*S = Ab@base_w + As . spline_w   grid (4 ntiles, 9 parts) */
__global__ void k_cur(const float* __restrict__ base_w, const float* __restrict__ spline_w)
{
    int n0 = blockIdx.x * 128;
    int part = blockIdx.y;
    if (part == 0)
        gemmW<0,0>(g_Ab, FF, nullptr, base_w, UU, g_cur, UU, n0, 0, FF);
    else
        gemmW<0,1>(g_As, FF * NBF, nullptr, spline_w, FF * NBF, g_cur, UU,
                   n0, (part - 1) * 128, 128);
}

/* 4 gate GEMMs, A = [cur/S | h_prev] built in A-load   grid (4, 4, 8) */
__global__ void k_lstm(const float* __restrict__ h_prev,
                       const float* __restrict__ wf, const float* __restrict__ wi,
                       const float* __restrict__ wc, const float* __restrict__ wo)
{
    const float* w = (blockIdx.y == 0) ? wf : (blockIdx.y == 1) ? wi
                   : (blockIdx.y == 2) ? wc : wo;
    float* o = g_gates + (size_t)blockIdx.y * BU;
    gemmW<3,0>(g_cur, UU, h_prev, w, UU, o, UU,
               blockIdx.x * 128, blockIdx.z * 128, 128);
}

/* gate nonlinearities + state update */
__global__ void k_fin(const float* __restrict__ c_prev,
                      const float* __restrict__ bf, const float* __restrict__ bi,
                      const float* __restrict__ bc, const float* __restrict__ bo,
                      float* __restrict__ out, int out_size)
{
    int i = blockIdx.x * blockDim.x + threadIdx.x;
    int u = i & (UU - 1);
    float fg = 1.f / (1.f + __expf(-(g_gates[i]          + bf[u])));
    float ig = 1.f / (1.f + __expf(-(g_gates[BU + i]     + bi[u])));
    float cd = tanhf(              g_gates[2 * BU + i]   + bc[u]);
    float og = 1.f / (1.f + __expf(-(g_gates[3 * BU + i] + bo[u])));
    float c = fg * c_prev[i] + ig * cd;
    float h = og * tanhf(c);
    out[i] = h;
    if (out_size >= 2 * BU) out[BU + i] = c;
}

/* ------------------------------------------------------------------ */
extern "C" void kernel_launch(void* const* d_in, const int* in_sizes, int n_in,
                              void* d_out, int out_size)
{
    const float* X       = (const float*)d_in[0];
    const float* h_prev  = (const float*)d_in[1];
    const float* c_prev  = (const float*)d_in[2];
    const float* tk      = (const float*)d_in[3];
    const float* base_w  = (const float*)d_in[4];
    const float* spl_w   = (const float*)d_in[5];
    const float* w1      = (const float*)d_in[6];
    const float* b1      = (const float*)d_in[7];
    const float* w2      = (const float*)d_in[8];
    const float* b2      = (const float*)d_in[9];
    const float* w3      = (const float*)d_in[10];
    const float* b3      = (const float*)d_in[11];
    const float* w4      = (const float*)d_in[12];
    const float* b4      = (const float*)d_in[13];
    const float* ws      = (const float*)d_in[14];
    const float* bs      = (const float*)d_in[15];
    const float* gamma   = (const float*)d_in[16];
    const float* beta    = (const float*)d_in[17];
    const float* wf      = (const float*)d_in[18];
    const float* bf      = (const float*)d_in[19];
    const float* wi      = (const float*)d_in[20];
    const float* bi      = (const float*)d_in[21];
    const float* wc      = (const float*)d_in[22];
    const float* bc      = (const float*)d_in[23];
    const float* wo      = (const float*)d_in[24];
    const float* bo      = (const float*)d_in[25];
    float* out = (float*)d_out;

    k_zero   <<<256, 256>>>();
    k_sig    <<<dim3(2, BB), 256>>>(X, tk);
    k_siggemm<<<dim3(8, 12, 2), 128>>>(w1, ws);
    k_h2     <<<dim3(4, 16), 256>>>(b1, w2);
    k_g34    <<<dim3(4, 8, 2), 256>>>(b2, w3, w4);
    k_lnsm   <<<BB, 512>>>(b3, b4, bs, gamma, beta);
    k_reduce <<<dim3(BB, 8), 128>>>(X, tk);
    k_cur    <<<dim3(4, 9), 256>>>(base_w, spl_w);
    k_lstm   <<<dim3(4, 4, 8), 256>>>(h_prev, wf, wi, wc, wo);
    k_fin    <<<BU / 256, 256>>>(c_prev, bf, bi, bc, bo, out, out_size);
}